// round 14
// baseline (speedup 1.0000x reference)
#include <cuda_runtime.h>
#include <cuda_bf16.h>
#include <math.h>
#include <stdint.h>

#define BB 128
#define TT 512
#define HH 1024
#define SS 128
#define KK 64
#define HIDV 512
#define DD 1152
#define G3 3072
#define GRID 128
#define NTHR 512
#define KTOT 1088
#define NCH 17
// k_seq smem byte offsets (stride 72 bf16 = 144 B rows)
#define A_HI 0
#define A_LO 4608
#define B_HI 9216
#define B_LO 23040
#define BUF_BYTES 36864
#define SMEM_DYN (2 * BUF_BYTES)
// k_gx smem offsets (stride 24 bf16 = 48 B rows), buffer = 24576 B
#define GA_HI 0
#define GA_LO 6144
#define GB_HI 12288
#define GB_LO 18432
#define GBUF 24576

// ---------------- scratch (device globals; no allocation allowed) ----------
__device__ float g_Gx[(size_t)TT * BB * G3];                 // [t][b][3H]
__device__ float g_hbuf[2][BB * HH];
__device__ float g_state[BB * KK];
__device__ float g_a1[BB * HIDV];
__device__ __align__(16) __nv_bfloat16 g_Bhi[(size_t)G3 * KTOT];
__device__ __align__(16) __nv_bfloat16 g_Blo[(size_t)G3 * KTOT];
__device__ __align__(16) __nv_bfloat16 g_Whi[(size_t)G3 * HH];
__device__ __align__(16) __nv_bfloat16 g_Wlo[(size_t)G3 * HH];
__device__ unsigned g_cnt;
__device__ unsigned g_epoch;

// ---------------- mma/ldmatrix helpers --------------------------------------
__device__ __forceinline__ void ldm4(uint32_t& r0, uint32_t& r1, uint32_t& r2,
                                     uint32_t& r3, uint32_t a) {
    asm volatile("ldmatrix.sync.aligned.m8n8.x4.shared.b16 {%0,%1,%2,%3}, [%4];"
                 : "=r"(r0), "=r"(r1), "=r"(r2), "=r"(r3) : "r"(a));
}
__device__ __forceinline__ void ldm2(uint32_t& r0, uint32_t& r1, uint32_t a) {
    asm volatile("ldmatrix.sync.aligned.m8n8.x2.shared.b16 {%0,%1}, [%2];"
                 : "=r"(r0), "=r"(r1) : "r"(a));
}
__device__ __forceinline__ void mma_bf16(float* c, uint32_t a0, uint32_t a1,
                                         uint32_t a2, uint32_t a3,
                                         uint32_t b0, uint32_t b1) {
    asm volatile("mma.sync.aligned.m16n8k16.row.col.f32.bf16.bf16.f32 "
                 "{%0,%1,%2,%3}, {%4,%5,%6,%7}, {%8,%9}, {%0,%1,%2,%3};"
                 : "+f"(c[0]), "+f"(c[1]), "+f"(c[2]), "+f"(c[3])
                 : "r"(a0), "r"(a1), "r"(a2), "r"(a3), "r"(b0), "r"(b1));
}
static __device__ __forceinline__ void split2(float a, float b,
                                              uint32_t& whi, uint32_t& wlo) {
    __nv_bfloat16 ha = __float2bfloat16(a), hb = __float2bfloat16(b);
    __nv_bfloat16 la = __float2bfloat16(a - __bfloat162float(ha));
    __nv_bfloat16 lb = __float2bfloat16(b - __bfloat162float(hb));
    whi = (uint32_t)__bfloat16_as_ushort(ha) | ((uint32_t)__bfloat16_as_ushort(hb) << 16);
    wlo = (uint32_t)__bfloat16_as_ushort(la) | ((uint32_t)__bfloat16_as_ushort(lb) << 16);
}

// ---------------- init ------------------------------------------------------
__global__ void k_init(const float* __restrict__ init_state) {
    int idx = blockIdx.x * blockDim.x + threadIdx.x;
    if (idx < BB * HH) g_hbuf[0][idx] = 0.0f;
    if (idx < BB * KK) g_state[idx] = init_state[idx];
    if (idx == 0) { g_cnt = 0u; g_epoch = 0u; }
}

// ---------------- k_prep: build B = [Whh | Mse^T] as bf16 hi/lo -------------
__global__ void k_prep(const float* __restrict__ Whh, const float* __restrict__ E,
                       const float* __restrict__ Wih) {
    int j = blockIdx.x;
    __shared__ float ws[SS];
    ws[threadIdx.x] = Wih[(size_t)j * DD + HH + threadIdx.x];
    __syncthreads();
    for (int col = threadIdx.x; col < KTOT; col += 128) {
        float v;
        if (col < HH) v = Whh[(size_t)j * HH + col];
        else {
            int kk = col - HH;
            float a = 0.0f;
#pragma unroll 8
            for (int s = 0; s < SS; s++) a += E[kk * SS + s] * ws[s];
            v = a;
        }
        __nv_bfloat16 hi = __float2bfloat16(v);
        __nv_bfloat16 lo = __float2bfloat16(v - __bfloat162float(hi));
        g_Bhi[(size_t)j * KTOT + col] = hi;
        g_Blo[(size_t)j * KTOT + col] = lo;
    }
}

// ---------------- k_prepw: split W_ih[:, :H] into bf16 hi/lo ----------------
__global__ void k_prepw(const float* __restrict__ Wih) {
    int j = blockIdx.x;
    for (int col = threadIdx.x; col < HH; col += 256) {
        float v = Wih[(size_t)j * DD + col];
        __nv_bfloat16 hi = __float2bfloat16(v);
        __nv_bfloat16 lo = __float2bfloat16(v - __bfloat162float(hi));
        g_Whi[(size_t)j * HH + col] = hi;
        g_Wlo[(size_t)j * HH + col] = lo;
    }
}

// ---------------- Gx = contexts @ W_ih[:, :H]^T + b_ih (bf16 hi/lo mma) -----
__global__ void __launch_bounds__(256, 2)
k_gx(const float* __restrict__ ctx, const float* __restrict__ bih) {
    __shared__ __align__(16) char sm[2][GBUF];
    const int tid = threadIdx.x, wid = tid >> 5, lane = tid & 31;
    const int m0 = blockIdx.y * 128, j0 = blockIdx.x * 128;
    const int wm = wid & 3, wn = wid >> 2;

    uint32_t sb;
    asm("{ .reg .u64 t; cvta.to.shared.u64 t, %1; cvt.u32.u64 %0, t; }"
        : "=r"(sb) : "l"((void*)sm));

    const int lr = tid >> 1;
    const int lc8 = (tid & 1) * 8;
    const float* actx = ctx + (size_t)(m0 + lr) * HH + lc8;
    const __nv_bfloat16* wh = g_Whi + (size_t)(j0 + lr) * HH + lc8;
    const __nv_bfloat16* wl = g_Wlo + (size_t)(j0 + lr) * HH + lc8;
    const int adst = lr * 48 + (tid & 1) * 16;

    int aoff[2], boff[4];
#pragma unroll
    for (int mt = 0; mt < 2; mt++)
        aoff[mt] = (wm * 32 + mt * 16 + (lane & 7) + ((lane & 8) ? 8 : 0)) * 48 +
                   ((lane & 16) ? 16 : 0);
#pragma unroll
    for (int nb = 0; nb < 4; nb++)
        boff[nb] = (wn * 64 + nb * 16 + (lane & 7) + ((lane & 16) ? 8 : 0)) * 48 +
                   ((lane & 8) ? 16 : 0);

    float acc[2][8][4];
#pragma unroll
    for (int i = 0; i < 2; i++)
#pragma unroll
        for (int j = 0; j < 8; j++)
#pragma unroll
            for (int q = 0; q < 4; q++) acc[i][j][q] = 0.0f;

    float4 v0, v1;
    uint4 bhv, blv;

    v0 = *(const float4*)(actx);
    v1 = *(const float4*)(actx + 4);
    bhv = *(const uint4*)(wh);
    blv = *(const uint4*)(wl);
    {
        uint32_t h0, l0, h1, l1, h2, l2, h3, l3;
        split2(v0.x, v0.y, h0, l0); split2(v0.z, v0.w, h1, l1);
        split2(v1.x, v1.y, h2, l2); split2(v1.z, v1.w, h3, l3);
        *(uint4*)(sm[0] + GA_HI + adst) = make_uint4(h0, h1, h2, h3);
        *(uint4*)(sm[0] + GA_LO + adst) = make_uint4(l0, l1, l2, l3);
        *(uint4*)(sm[0] + GB_HI + adst) = bhv;
        *(uint4*)(sm[0] + GB_LO + adst) = blv;
    }
    __syncthreads();

    for (int c = 0; c < 64; c++) {
        if (c < 63) {
            int k0 = (c + 1) * 16;
            v0 = *(const float4*)(actx + k0);
            v1 = *(const float4*)(actx + k0 + 4);
            bhv = *(const uint4*)(wh + k0);
            blv = *(const uint4*)(wl + k0);
        }
        const uint32_t bufs = sb + (c & 1) * GBUF;
#pragma unroll
        for (int mt = 0; mt < 2; mt++) {
            uint32_t ah0, ah1, ah2, ah3, al0, al1, al2, al3;
            ldm4(ah0, ah1, ah2, ah3, bufs + GA_HI + aoff[mt]);
            ldm4(al0, al1, al2, al3, bufs + GA_LO + aoff[mt]);
#pragma unroll
            for (int nb = 0; nb < 4; nb++) {
                uint32_t bh0, bh1, bh2, bh3, bl0, bl1, bl2, bl3;
                ldm4(bh0, bh1, bh2, bh3, bufs + GB_HI + boff[nb]);
                ldm4(bl0, bl1, bl2, bl3, bufs + GB_LO + boff[nb]);
                float* c0 = acc[mt][nb * 2];
                float* c1 = acc[mt][nb * 2 + 1];
                mma_bf16(c0, ah0, ah1, ah2, ah3, bh0, bh1);
                mma_bf16(c0, ah0, ah1, ah2, ah3, bl0, bl1);
                mma_bf16(c0, al0, al1, al2, al3, bh0, bh1);
                mma_bf16(c1, ah0, ah1, ah2, ah3, bh2, bh3);
                mma_bf16(c1, ah0, ah1, ah2, ah3, bl2, bl3);
                mma_bf16(c1, al0, al1, al2, al3, bh2, bh3);
            }
        }
        if (c < 63) {
            char* nb2 = sm[(c + 1) & 1];
            uint32_t h0, l0, h1, l1, h2, l2, h3, l3;
            split2(v0.x, v0.y, h0, l0); split2(v0.z, v0.w, h1, l1);
            split2(v1.x, v1.y, h2, l2); split2(v1.z, v1.w, h3, l3);
            *(uint4*)(nb2 + GA_HI + adst) = make_uint4(h0, h1, h2, h3);
            *(uint4*)(nb2 + GA_LO + adst) = make_uint4(l0, l1, l2, l3);
            *(uint4*)(nb2 + GB_HI + adst) = bhv;
            *(uint4*)(nb2 + GB_LO + adst) = blv;
        }
        __syncthreads();
    }

#pragma unroll
    for (int mt = 0; mt < 2; mt++) {
#pragma unroll
        for (int nt = 0; nt < 8; nt++) {
            int col = j0 + wn * 64 + nt * 8 + (lane & 3) * 2;
            float bi0 = bih[col], bi1 = bih[col + 1];
#pragma unroll
            for (int rr = 0; rr < 2; rr++) {
                int m = m0 + wm * 32 + mt * 16 + (lane >> 2) + rr * 8;
                int bb = m >> 9, tt = m & 511;
                float2 val = make_float2(acc[mt][nt][rr * 2] + bi0,
                                         acc[mt][nt][rr * 2 + 1] + bi1);
                *(float2*)(g_Gx + ((size_t)tt * BB + bb) * G3 + col) = val;
            }
        }
    }
}

// ---------------- software grid barrier -------------------------------------
__device__ __forceinline__ void gsync(unsigned target) {
    __syncthreads();
    if (threadIdx.x == 0) {
        __threadfence();
        if (atomicAdd(&g_cnt, 1u) == GRID - 1u) {
            g_cnt = 0u;
            __threadfence();
            atomicExch(&g_epoch, target);
        } else {
            while (*(volatile unsigned*)&g_epoch < target) { __nanosleep(64); }
        }
        __threadfence();
    }
    __syncthreads();
}

// ---------------- persistent sequence kernel --------------------------------
// Phase A: 16-warp k-split mma.sync bf16 hi/lo; Gx prefetched to registers.
// Phase B: 8x 64-wide k chunks per split-k group, double-buffered smem.
__global__ void __launch_bounds__(NTHR, 1)
k_seq(const float* __restrict__ bhh,
      const float* __restrict__ W1, const float* __restrict__ b1,
      const float* __restrict__ W2, const float* __restrict__ b2,
      float* __restrict__ out)
{
    extern __shared__ char dsm[];
    float* shf = (float*)dsm;
    const int tid = threadIdx.x;
    const int blk = blockIdx.x;
    unsigned bar = 1;

    uint32_t sbase;
    asm("{ .reg .u64 t; cvta.to.shared.u64 t, %1; cvt.u32.u64 %0, t; }"
        : "=r"(sbase) : "l"(dsm));

    const int a_b0 = (blk >> 5) * 32;
    const int a_i0 = (blk & 31) * 32;

    // ---- mma mapping: all 16 warps, k-split by kg ----
    const int wid = tid >> 5, lane = tid & 31;
    const int kg = wid >> 3;            // ks-group: 0 -> ks{0,1}, 1 -> ks{2,3}
    const int w8 = wid & 7;
    const int mt = w8 & 1;
    const int np = w8 >> 1;
    const int ksbase = kg * 64;         // byte offset of first ks (2*32)
    const int aoff = ((mt * 16 + (lane & 7) + ((lane & 8) ? 8 : 0)) * 72 +
                      ((lane & 16) ? 8 : 0)) * 2;
    const int boff4 = ((np * 24 + (lane & 7) + ((lane & 16) ? 8 : 0)) * 72 +
                       ((lane & 8) ? 8 : 0)) * 2;
    const int boff2 = ((np * 24 + 16 + (lane & 7)) * 72 +
                       ((lane & 8) ? 8 : 0)) * 2;

    // ---- A loader: 1 float4 per thread per chunk ----
    const int l_arow = tid >> 4;
    const int l_af4  = tid & 15;
    const int a_dst  = l_arow * 144 + l_af4 * 8;

    // ---- B loader: 3 uint4 per thread per chunk ----
    const __nv_bfloat16* b_basep[3];
    size_t b_off[3];
    int b_dst[3];
#pragma unroll
    for (int q = 0; q < 3; q++) {
        int idx = tid + 512 * q;
        bool hi = idx < 768;
        int idx2 = hi ? idx : idx - 768;
        int row = idx2 >> 3, seg = idx2 & 7;
        int jg = a_i0 + (row < 32 ? row : row < 64 ? 992 + row : 1984 + row);
        b_basep[q] = hi ? g_Bhi : g_Blo;
        b_off[q] = (size_t)jg * KTOT + seg * 8;
        b_dst[q] = (hi ? B_HI : B_LO) + row * 144 + seg * 16;
    }

    // Phase B/C mapping
    const int g  = tid >> 8;
    const int t2 = tid & 255;

    for (int t = 0; t < TT; t++) {
        const float* hcur = g_hbuf[t & 1];
        float* hnxt = g_hbuf[(t & 1) ^ 1];

        // ---- prefetch this step's Gx gate values into registers ----
        float gR[2], gZ[2], gN[2];
        {
            const float* gx = g_Gx + ((size_t)t * BB + a_b0) * G3;
#pragma unroll
            for (int rep = 0; rep < 2; rep++) {
                int idx = tid + rep * 512;
                int b = idx >> 5, i = idx & 31;
                int ii = a_i0 + i;
                const float* gxb = gx + (size_t)b * G3;
                gR[rep] = gxb[ii];
                gZ[rep] = gxb[1024 + ii];
                gN[rep] = gxb[2048 + ii];
            }
        }

        // ================= Phase A: mma.sync bf16-split GEMM ===============
        float cH[3][4] = {}, cS[3][4] = {};
        float4 aP;
        uint4 bP0, bP1, bP2;

        aP = *(const float4*)(hcur + (size_t)(a_b0 + l_arow) * HH + l_af4 * 4);
        bP0 = *(const uint4*)(b_basep[0] + b_off[0]);
        bP1 = *(const uint4*)(b_basep[1] + b_off[1]);
        bP2 = *(const uint4*)(b_basep[2] + b_off[2]);
        {
            uint32_t h01, l01, h23, l23;
            split2(aP.x, aP.y, h01, l01);
            split2(aP.z, aP.w, h23, l23);
            *(uint2*)(dsm + A_HI + a_dst) = make_uint2(h01, h23);
            *(uint2*)(dsm + A_LO + a_dst) = make_uint2(l01, l23);
            *(uint4*)(dsm + b_dst[0]) = bP0;
            *(uint4*)(dsm + b_dst[1]) = bP1;
            *(uint4*)(dsm + b_dst[2]) = bP2;
        }
        __syncthreads();

        for (int c = 0; c < NCH; c++) {
            const uint32_t bufs = sbase + (c & 1) * BUF_BYTES;
            if (c < NCH - 1) {
                int cn = c + 1;
                const float* asrc = (cn < 16)
                    ? (hcur + (size_t)(a_b0 + l_arow) * HH + cn * 64 + l_af4 * 4)
                    : (g_state + (size_t)(a_b0 + l_arow) * KK + l_af4 * 4);
                aP = *(const float4*)asrc;
                bP0 = *(const uint4*)(b_basep[0] + b_off[0] + cn * 64);
                bP1 = *(const uint4*)(b_basep[1] + b_off[1] + cn * 64);
                bP2 = *(const uint4*)(b_basep[2] + b_off[2] + cn * 64);
            }
            {
                float (*cc)[4] = (c == 16) ? cS : cH;
#pragma unroll
                for (int kss = 0; kss < 2; kss++) {
                    const uint32_t koff = ksbase + kss * 32;
                    uint32_t ah0, ah1, ah2, ah3, al0, al1, al2, al3;
                    ldm4(ah0, ah1, ah2, ah3, bufs + A_HI + aoff + koff);
                    ldm4(al0, al1, al2, al3, bufs + A_LO + aoff + koff);
                    uint32_t bh0, bh1, bh2, bh3, bh4, bh5;
                    ldm4(bh0, bh1, bh2, bh3, bufs + B_HI + boff4 + koff);
                    ldm2(bh4, bh5,           bufs + B_HI + boff2 + koff);
                    uint32_t bl0, bl1, bl2, bl3, bl4, bl5;
                    ldm4(bl0, bl1, bl2, bl3, bufs + B_LO + boff4 + koff);
                    ldm2(bl4, bl5,           bufs + B_LO + boff2 + koff);
                    mma_bf16(cc[0], ah0, ah1, ah2, ah3, bh0, bh1);
                    mma_bf16(cc[0], ah0, ah1, ah2, ah3, bl0, bl1);
                    mma_bf16(cc[0], al0, al1, al2, al3, bh0, bh1);
                    mma_bf16(cc[1], ah0, ah1, ah2, ah3, bh2, bh3);
                    mma_bf16(cc[1], ah0, ah1, ah2, ah3, bl2, bl3);
                    mma_bf16(cc[1], al0, al1, al2, al3, bh2, bh3);
                    mma_bf16(cc[2], ah0, ah1, ah2, ah3, bh4, bh5);
                    mma_bf16(cc[2], ah0, ah1, ah2, ah3, bl4, bl5);
                    mma_bf16(cc[2], al0, al1, al2, al3, bh4, bh5);
                }
            }
            if (c < NCH - 1) {
                char* nb = dsm + ((c + 1) & 1) * BUF_BYTES;
                uint32_t h01, l01, h23, l23;
                split2(aP.x, aP.y, h01, l01);
                split2(aP.z, aP.w, h23, l23);
                *(uint2*)(nb + A_HI + a_dst) = make_uint2(h01, h23);
                *(uint2*)(nb + A_LO + a_dst) = make_uint2(l01, l23);
                *(uint4*)(nb + b_dst[0]) = bP0;
                *(uint4*)(nb + b_dst[1]) = bP1;
                *(uint4*)(nb + b_dst[2]) = bP2;
            }
            __syncthreads();
        }

        // ---- stage fragments: H0,H1,S0,S1 regions of [96][33] floats ----
        {
            float* preH = shf + kg * 3168;
            float* preS = shf + 6336 + kg * 3168;
            const int rb = mt * 16 + (lane >> 2);
#pragma unroll
            for (int tau = 0; tau < 3; tau++) {
                int jc = np * 24 + tau * 8 + (lane & 3) * 2;
                preH[jc * 33 + rb]           = cH[tau][0];
                preH[(jc + 1) * 33 + rb]     = cH[tau][1];
                preH[jc * 33 + rb + 8]       = cH[tau][2];
                preH[(jc + 1) * 33 + rb + 8] = cH[tau][3];
                preS[jc * 33 + rb]           = cS[tau][0];
                preS[(jc + 1) * 33 + rb]     = cS[tau][1];
                preS[jc * 33 + rb + 8]       = cS[tau][2];
                preS[(jc + 1) * 33 + rb + 8] = cS[tau][3];
            }
            __syncthreads();

            // ---- gate epilogue -> h_new ----
#pragma unroll
            for (int rep = 0; rep < 2; rep++) {
                int idx = tid + rep * 512;
                int b = idx >> 5, i = idx & 31;
                int ii = a_i0 + i;
                int e0 = i * 33 + b, e1 = (32 + i) * 33 + b, e2 = (64 + i) * 33 + b;
                float Sr = shf[e0] + shf[3168 + e0] + shf[6336 + e0] +
                           shf[9504 + e0] + gR[rep] + bhh[ii];
                float Sz = shf[e1] + shf[3168 + e1] + shf[6336 + e1] +
                           shf[9504 + e1] + gZ[rep] + bhh[1024 + ii];
                float An = shf[6336 + e2] + shf[9504 + e2] + gN[rep];
                float Hn = shf[e2] + shf[3168 + e2] + bhh[2048 + ii];
                float r = 1.0f / (1.0f + expf(-Sr));
                float z = 1.0f / (1.0f + expf(-Sz));
                float n = tanhf(An + r * Hn);
                hnxt[(size_t)(a_b0 + b) * HH + ii] =
                    (1.0f - z) * n + z * hcur[(size_t)(a_b0 + b) * HH + ii];
            }
        }
        gsync(bar++);

        // ========== Phase B: a1 = tanh(h_new @ W1^T + b1) ==================
        // split-k x2 groups (512 k each), 8 chunks of 64, double-buffered.
        {
            const int b_o0 = (blk & 31) * 16;
            const int bty = t2 >> 3;
            const int btx = t2 & 7;
            const int hrow = t2 & 31, hk8 = (t2 >> 5) * 8;
            const int wrow = t2 & 15, wk4 = (t2 >> 4) * 4;
            float* HB0 = shf + (g * 2) * 2048;
            float* HB1 = shf + (g * 2 + 1) * 2048;
            float* WB0 = shf + 8192 + (g * 2) * 1024;
            float* WB1 = shf + 8192 + (g * 2 + 1) * 1024;
            const float* hsrc = hnxt + (size_t)(a_b0 + hrow) * HH + g * 512 + hk8;
            const float* wsrc = W1 + (size_t)(b_o0 + wrow) * HH + g * 512 + wk4;

            float c0 = 0.0f, c1 = 0.0f;
            float4 h0 = *(const float4*)hsrc;
            float4 h1 = *(const float4*)(hsrc + 4);
            float4 wv = *(const float4*)wsrc;
            HB0[(hk8 + 0) * 32 + hrow] = h0.x; HB0[(hk8 + 1) * 32 + hrow] = h0.y;
            HB0[(hk8 + 2) * 32 + hrow] = h0.z; HB0[(hk8 + 3) * 32 + hrow] = h0.w;
            HB0[(hk8 + 4) * 32 + hrow] = h1.x; HB0[(hk8 + 5) * 32 + hrow] = h1.y;
            HB0[(hk8 + 6) * 32 + hrow] = h1.z; HB0[(hk8 + 7) * 32 + hrow] = h1.w;
            WB0[(wk4 + 0) * 16 + wrow] = wv.x; WB0[(wk4 + 1) * 16 + wrow] = wv.y;
            WB0[(wk4 + 2) * 16 + wrow] = wv.z; WB0[(wk4 + 3) * 16 + wrow] = wv.w;
            __syncthreads();

            for (int kt = 0; kt < 8; kt++) {
                if (kt < 7) {
                    int k0 = (kt + 1) * 64;
                    h0 = *(const float4*)(hsrc + k0);
                    h1 = *(const float4*)(hsrc + k0 + 4);
                    wv = *(const float4*)(wsrc + k0);
                }
                const float* hb = (kt & 1) ? HB1 : HB0;
                const float* wb = (kt & 1) ? WB1 : WB0;
#pragma unroll
                for (int k = 0; k < 64; k++) {
                    float a = hb[k * 32 + bty];
                    float2 w = *(const float2*)&wb[k * 16 + btx * 2];
                    c0 += a * w.x; c1 += a * w.y;
                }
                if (kt < 7) {
                    float* hbn = (kt & 1) ? HB0 : HB1;
                    float* wbn = (kt & 1) ? WB0 : WB1;
                    hbn[(hk8 + 0) * 32 + hrow] = h0.x; hbn[(hk8 + 1) * 32 + hrow] = h0.y;
                    hbn[(hk8 + 2) * 32 + hrow] = h0.z; hbn[(hk8 + 3) * 32 + hrow] = h0.w;
                    hbn[(hk8 + 4) * 32 + hrow] = h1.x; hbn[(hk8 + 5) * 32 + hrow] = h1.y;
                    hbn[(hk8 + 6) * 32 + hrow] = h1.z; hbn[(hk8 + 7) * 32 + hrow] = h1.w;
                    wbn[(wk4 + 0) * 16 + wrow] = wv.x; wbn[(wk4 + 1) * 16 + wrow] = wv.y;
                    wbn[(wk4 + 2) * 16 + wrow] = wv.z; wbn[(wk4 + 3) * 16 + wrow] = wv.w;
                }
                __syncthreads();
            }

            if (g == 1) {
                shf[12288 + t2 * 2] = c0; shf[12288 + t2 * 2 + 1] = c1;
            }
            __syncthreads();
            if (g == 0) {
                c0 += shf[12288 + t2 * 2]; c1 += shf[12288 + t2 * 2 + 1];
                int b = a_b0 + bty, o = b_o0 + btx * 2;
                g_a1[b * HIDV + o]     = tanhf(c0 + b1[o]);
                g_a1[b * HIDV + o + 1] = tanhf(c1 + b1[o + 1]);
            }
        }
        gsync(bar++);

        // ========== Phase C: logits + softmax state, split-k x8 ============
        {
            int b = blk;
            shf[tid] = g_a1[b * HIDV + tid];
            __syncthreads();
            int k = tid & 63, q = tid >> 6;
            const float* w = W2 + (size_t)k * HIDV + q * 64;
            const float* a = shf + q * 64;
            float p = 0.0f;
#pragma unroll 16
            for (int i = 0; i < 64; i++) p += a[i] * w[i];
            shf[512 + tid] = p;
            __syncthreads();
            if (tid < KK) {
                float lg = b2[tid];
#pragma unroll
                for (int q2 = 0; q2 < 8; q2++) lg += shf[512 + q2 * 64 + tid];
                out[((size_t)b * TT + t) * KK + tid] = lg;
                shf[1024 + tid] = fminf(fmaxf(lg, -10.0f), 10.0f);
            }
            __syncthreads();
            if (tid < 32) {
                float x0 = shf[1024 + tid], x1 = shf[1024 + tid + 32];
                float m = fmaxf(x0, x1);
#pragma unroll
                for (int o = 16; o; o >>= 1) m = fmaxf(m, __shfl_xor_sync(0xffffffffu, m, o));
                float e0 = expf(x0 - m), e1 = expf(x1 - m);
                float s = e0 + e1;
#pragma unroll
                for (int o = 16; o; o >>= 1) s += __shfl_xor_sync(0xffffffffu, s, o);
                float inv = 1.0f / s;
                g_state[b * KK + tid]      = e0 * inv;
                g_state[b * KK + tid + 32] = e1 * inv;
            }
        }
        gsync(bar++);
    }
}

// ---------------- host launch -----------------------------------------------
extern "C" void kernel_launch(void* const* d_in, const int* in_sizes, int n_in,
                              void* d_out, int out_size) {
    const float* ctx  = (const float*)d_in[0];   // [B,T,H]
    const float* init = (const float*)d_in[1];   // [B,K]
    const float* E    = (const float*)d_in[2];   // [K,S]
    const float* Wih  = (const float*)d_in[3];   // [3H,D]
    const float* Whh  = (const float*)d_in[4];   // [3H,H]
    const float* bih  = (const float*)d_in[5];   // [3H]
    const float* bhh  = (const float*)d_in[6];   // [3H]
    const float* W1   = (const float*)d_in[7];   // [HID,H]
    const float* b1   = (const float*)d_in[8];   // [HID]
    const float* W2   = (const float*)d_in[9];   // [K,HID]
    const float* b2   = (const float*)d_in[10];  // [K]
    float* out = (float*)d_out;                  // [B,T,K] fp32

    cudaFuncSetAttribute(k_seq, cudaFuncAttributeMaxDynamicSharedMemorySize, SMEM_DYN);

    k_init<<<512, 256>>>(init);
    k_prep<<<G3, 128>>>(Whh, E, Wih);
    k_prepw<<<G3, 256>>>(Wih);
    k_gx<<<dim3(G3 / 128, (BB * TT) / 128), 256>>>(ctx, bih);
    k_seq<<<GRID, NTHR, SMEM_DYN>>>(bhh, W1, b1, W2, b2, out);
}

// round 15
// speedup vs baseline: 1.2195x; 1.2195x over previous
#include <cuda_runtime.h>
#include <cuda_bf16.h>
#include <math.h>
#include <stdint.h>

#define BB 128
#define TT 512
#define HH 1024
#define SS 128
#define KK 64
#define HIDV 512
#define DD 1152
#define G3 3072
#define GRID 128
#define NTHR 512
#define KTOT 1088
#define NCH 17
// k_seq smem byte offsets (stride 72 bf16 = 144 B rows)
#define A_HI 0
#define A_LO 4608
#define B_HI 9216
#define B_LO 23040
#define BUF_BYTES 36864
#define SMEM_DYN (2 * BUF_BYTES)
// k_gx smem offsets (stride 24 bf16 = 48 B rows), buffer = 24576 B
#define GA_HI 0
#define GA_LO 6144
#define GB_HI 12288
#define GB_LO 18432
#define GBUF 24576

// ---------------- scratch (device globals; no allocation allowed) ----------
__device__ float g_Gx[(size_t)TT * BB * G3];                 // [t][b][3H]
__device__ float g_hbuf[2][BB * HH];
__device__ float g_state[BB * KK];
__device__ float g_a1[BB * HIDV];
__device__ __align__(16) __nv_bfloat16 g_Bhi[(size_t)G3 * KTOT];
__device__ __align__(16) __nv_bfloat16 g_Blo[(size_t)G3 * KTOT];
__device__ __align__(16) __nv_bfloat16 g_Whi[(size_t)G3 * HH];
__device__ __align__(16) __nv_bfloat16 g_Wlo[(size_t)G3 * HH];
__device__ unsigned g_cnt;
__device__ unsigned g_epoch;

// ---------------- mma/ldmatrix helpers --------------------------------------
__device__ __forceinline__ void ldm4(uint32_t& r0, uint32_t& r1, uint32_t& r2,
                                     uint32_t& r3, uint32_t a) {
    asm volatile("ldmatrix.sync.aligned.m8n8.x4.shared.b16 {%0,%1,%2,%3}, [%4];"
                 : "=r"(r0), "=r"(r1), "=r"(r2), "=r"(r3) : "r"(a));
}
__device__ __forceinline__ void ldm2(uint32_t& r0, uint32_t& r1, uint32_t a) {
    asm volatile("ldmatrix.sync.aligned.m8n8.x2.shared.b16 {%0,%1}, [%2];"
                 : "=r"(r0), "=r"(r1) : "r"(a));
}
__device__ __forceinline__ void mma_bf16(float* c, uint32_t a0, uint32_t a1,
                                         uint32_t a2, uint32_t a3,
                                         uint32_t b0, uint32_t b1) {
    asm volatile("mma.sync.aligned.m16n8k16.row.col.f32.bf16.bf16.f32 "
                 "{%0,%1,%2,%3}, {%4,%5,%6,%7}, {%8,%9}, {%0,%1,%2,%3};"
                 : "+f"(c[0]), "+f"(c[1]), "+f"(c[2]), "+f"(c[3])
                 : "r"(a0), "r"(a1), "r"(a2), "r"(a3), "r"(b0), "r"(b1));
}
static __device__ __forceinline__ void split2(float a, float b,
                                              uint32_t& whi, uint32_t& wlo) {
    __nv_bfloat16 ha = __float2bfloat16(a), hb = __float2bfloat16(b);
    __nv_bfloat16 la = __float2bfloat16(a - __bfloat162float(ha));
    __nv_bfloat16 lb = __float2bfloat16(b - __bfloat162float(hb));
    whi = (uint32_t)__bfloat16_as_ushort(ha) | ((uint32_t)__bfloat16_as_ushort(hb) << 16);
    wlo = (uint32_t)__bfloat16_as_ushort(la) | ((uint32_t)__bfloat16_as_ushort(lb) << 16);
}
// fast gate transcendentals (absolute error ~1e-7; safe at extremes)
static __device__ __forceinline__ float fsig(float x) {
    return __fdividef(1.0f, 1.0f + __expf(-x));
}
static __device__ __forceinline__ float ftanh(float x) {
    x = fminf(fmaxf(x, -9.0f), 9.0f);
    float t = __expf(2.0f * x);
    return __fdividef(t - 1.0f, t + 1.0f);
}

// ---------------- init ------------------------------------------------------
__global__ void k_init(const float* __restrict__ init_state) {
    int idx = blockIdx.x * blockDim.x + threadIdx.x;
    if (idx < BB * HH) g_hbuf[0][idx] = 0.0f;
    if (idx < BB * KK) g_state[idx] = init_state[idx];
    if (idx == 0) { g_cnt = 0u; g_epoch = 0u; }
}

// ---------------- k_prep: build B = [Whh | Mse^T] as bf16 hi/lo -------------
__global__ void k_prep(const float* __restrict__ Whh, const float* __restrict__ E,
                       const float* __restrict__ Wih) {
    int j = blockIdx.x;
    __shared__ float ws[SS];
    ws[threadIdx.x] = Wih[(size_t)j * DD + HH + threadIdx.x];
    __syncthreads();
    for (int col = threadIdx.x; col < KTOT; col += 128) {
        float v;
        if (col < HH) v = Whh[(size_t)j * HH + col];
        else {
            int kk = col - HH;
            float a = 0.0f;
#pragma unroll 8
            for (int s = 0; s < SS; s++) a += E[kk * SS + s] * ws[s];
            v = a;
        }
        __nv_bfloat16 hi = __float2bfloat16(v);
        __nv_bfloat16 lo = __float2bfloat16(v - __bfloat162float(hi));
        g_Bhi[(size_t)j * KTOT + col] = hi;
        g_Blo[(size_t)j * KTOT + col] = lo;
    }
}

// ---------------- k_prepw: split W_ih[:, :H] into bf16 hi/lo ----------------
__global__ void k_prepw(const float* __restrict__ Wih) {
    int j = blockIdx.x;
    for (int col = threadIdx.x; col < HH; col += 256) {
        float v = Wih[(size_t)j * DD + col];
        __nv_bfloat16 hi = __float2bfloat16(v);
        __nv_bfloat16 lo = __float2bfloat16(v - __bfloat162float(hi));
        g_Whi[(size_t)j * HH + col] = hi;
        g_Wlo[(size_t)j * HH + col] = lo;
    }
}

// ---------------- Gx = contexts @ W_ih[:, :H]^T + b_ih (bf16 hi/lo mma) -----
__global__ void __launch_bounds__(256, 2)
k_gx(const float* __restrict__ ctx, const float* __restrict__ bih) {
    __shared__ __align__(16) char sm[2][GBUF];
    const int tid = threadIdx.x, wid = tid >> 5, lane = tid & 31;
    const int m0 = blockIdx.y * 128, j0 = blockIdx.x * 128;
    const int wm = wid & 3, wn = wid >> 2;

    uint32_t sb;
    asm("{ .reg .u64 t; cvta.to.shared.u64 t, %1; cvt.u32.u64 %0, t; }"
        : "=r"(sb) : "l"((void*)sm));

    const int lr = tid >> 1;
    const int lc8 = (tid & 1) * 8;
    const float* actx = ctx + (size_t)(m0 + lr) * HH + lc8;
    const __nv_bfloat16* wh = g_Whi + (size_t)(j0 + lr) * HH + lc8;
    const __nv_bfloat16* wl = g_Wlo + (size_t)(j0 + lr) * HH + lc8;
    const int adst = lr * 48 + (tid & 1) * 16;

    int aoff[2], boff[4];
#pragma unroll
    for (int mt = 0; mt < 2; mt++)
        aoff[mt] = (wm * 32 + mt * 16 + (lane & 7) + ((lane & 8) ? 8 : 0)) * 48 +
                   ((lane & 16) ? 16 : 0);
#pragma unroll
    for (int nb = 0; nb < 4; nb++)
        boff[nb] = (wn * 64 + nb * 16 + (lane & 7) + ((lane & 16) ? 8 : 0)) * 48 +
                   ((lane & 8) ? 16 : 0);

    float acc[2][8][4];
#pragma unroll
    for (int i = 0; i < 2; i++)
#pragma unroll
        for (int j = 0; j < 8; j++)
#pragma unroll
            for (int q = 0; q < 4; q++) acc[i][j][q] = 0.0f;

    float4 v0, v1;
    uint4 bhv, blv;

    v0 = *(const float4*)(actx);
    v1 = *(const float4*)(actx + 4);
    bhv = *(const uint4*)(wh);
    blv = *(const uint4*)(wl);
    {
        uint32_t h0, l0, h1, l1, h2, l2, h3, l3;
        split2(v0.x, v0.y, h0, l0); split2(v0.z, v0.w, h1, l1);
        split2(v1.x, v1.y, h2, l2); split2(v1.z, v1.w, h3, l3);
        *(uint4*)(sm[0] + GA_HI + adst) = make_uint4(h0, h1, h2, h3);
        *(uint4*)(sm[0] + GA_LO + adst) = make_uint4(l0, l1, l2, l3);
        *(uint4*)(sm[0] + GB_HI + adst) = bhv;
        *(uint4*)(sm[0] + GB_LO + adst) = blv;
    }
    __syncthreads();

    for (int c = 0; c < 64; c++) {
        if (c < 63) {
            int k0 = (c + 1) * 16;
            v0 = *(const float4*)(actx + k0);
            v1 = *(const float4*)(actx + k0 + 4);
            bhv = *(const uint4*)(wh + k0);
            blv = *(const uint4*)(wl + k0);
        }
        const uint32_t bufs = sb + (c & 1) * GBUF;
#pragma unroll
        for (int mt = 0; mt < 2; mt++) {
            uint32_t ah0, ah1, ah2, ah3, al0, al1, al2, al3;
            ldm4(ah0, ah1, ah2, ah3, bufs + GA_HI + aoff[mt]);
            ldm4(al0, al1, al2, al3, bufs + GA_LO + aoff[mt]);
#pragma unroll
            for (int nb = 0; nb < 4; nb++) {
                uint32_t bh0, bh1, bh2, bh3, bl0, bl1, bl2, bl3;
                ldm4(bh0, bh1, bh2, bh3, bufs + GB_HI + boff[nb]);
                ldm4(bl0, bl1, bl2, bl3, bufs + GB_LO + boff[nb]);
                float* c0 = acc[mt][nb * 2];
                float* c1 = acc[mt][nb * 2 + 1];
                mma_bf16(c0, ah0, ah1, ah2, ah3, bh0, bh1);
                mma_bf16(c0, ah0, ah1, ah2, ah3, bl0, bl1);
                mma_bf16(c0, al0, al1, al2, al3, bh0, bh1);
                mma_bf16(c1, ah0, ah1, ah2, ah3, bh2, bh3);
                mma_bf16(c1, ah0, ah1, ah2, ah3, bl2, bl3);
                mma_bf16(c1, al0, al1, al2, al3, bh2, bh3);
            }
        }
        if (c < 63) {
            char* nb2 = sm[(c + 1) & 1];
            uint32_t h0, l0, h1, l1, h2, l2, h3, l3;
            split2(v0.x, v0.y, h0, l0); split2(v0.z, v0.w, h1, l1);
            split2(v1.x, v1.y, h2, l2); split2(v1.z, v1.w, h3, l3);
            *(uint4*)(nb2 + GA_HI + adst) = make_uint4(h0, h1, h2, h3);
            *(uint4*)(nb2 + GA_LO + adst) = make_uint4(l0, l1, l2, l3);
            *(uint4*)(nb2 + GB_HI + adst) = bhv;
            *(uint4*)(nb2 + GB_LO + adst) = blv;
        }
        __syncthreads();
    }

#pragma unroll
    for (int mt = 0; mt < 2; mt++) {
#pragma unroll
        for (int nt = 0; nt < 8; nt++) {
            int col = j0 + wn * 64 + nt * 8 + (lane & 3) * 2;
            float bi0 = bih[col], bi1 = bih[col + 1];
#pragma unroll
            for (int rr = 0; rr < 2; rr++) {
                int m = m0 + wm * 32 + mt * 16 + (lane >> 2) + rr * 8;
                int bb = m >> 9, tt = m & 511;
                float2 val = make_float2(acc[mt][nt][rr * 2] + bi0,
                                         acc[mt][nt][rr * 2 + 1] + bi1);
                *(float2*)(g_Gx + ((size_t)tt * BB + bb) * G3 + col) = val;
            }
        }
    }
}

// ---------------- software grid barrier -------------------------------------
__device__ __forceinline__ void gsync(unsigned target) {
    __syncthreads();
    if (threadIdx.x == 0) {
        __threadfence();
        if (atomicAdd(&g_cnt, 1u) == GRID - 1u) {
            g_cnt = 0u;
            __threadfence();
            atomicExch(&g_epoch, target);
        } else {
            while (*(volatile unsigned*)&g_epoch < target) { __nanosleep(64); }
        }
        __threadfence();
    }
    __syncthreads();
}

// ---------------- persistent sequence kernel (R12 structure) ----------------
__global__ void __launch_bounds__(NTHR, 1)
k_seq(const float* __restrict__ bhh,
      const float* __restrict__ W1, const float* __restrict__ b1,
      const float* __restrict__ W2, const float* __restrict__ b2,
      float* __restrict__ out)
{
    extern __shared__ char dsm[];
    float* shf = (float*)dsm;
    const int tid = threadIdx.x;
    const int blk = blockIdx.x;
    unsigned bar = 1;

    uint32_t sbase;
    asm("{ .reg .u64 t; cvta.to.shared.u64 t, %1; cvt.u32.u64 %0, t; }"
        : "=r"(sbase) : "l"(dsm));

    const int a_b0 = (blk >> 5) * 32;
    const int a_i0 = (blk & 31) * 32;

    const int wid = tid >> 5, lane = tid & 31;
    const bool mmaw = (wid < 8);
    const int mt = wid & 1;
    const int np = wid >> 1;
    const int aoff = ((mt * 16 + (lane & 7) + ((lane & 8) ? 8 : 0)) * 72 +
                      ((lane & 16) ? 8 : 0)) * 2;
    const int boff4 = ((np * 24 + (lane & 7) + ((lane & 16) ? 8 : 0)) * 72 +
                       ((lane & 8) ? 8 : 0)) * 2;
    const int boff2 = ((np * 24 + 16 + (lane & 7)) * 72 +
                       ((lane & 8) ? 8 : 0)) * 2;

    const int l_arow = tid >> 4;
    const int l_af4  = tid & 15;
    const int a_dst  = l_arow * 144 + l_af4 * 8;

    const __nv_bfloat16* b_basep[3];
    size_t b_off[3];
    int b_dst[3];
#pragma unroll
    for (int q = 0; q < 3; q++) {
        int idx = tid + 512 * q;
        bool hi = idx < 768;
        int idx2 = hi ? idx : idx - 768;
        int row = idx2 >> 3, seg = idx2 & 7;
        int jg = a_i0 + (row < 32 ? row : row < 64 ? 992 + row : 1984 + row);
        b_basep[q] = hi ? g_Bhi : g_Blo;
        b_off[q] = (size_t)jg * KTOT + seg * 8;
        b_dst[q] = (hi ? B_HI : B_LO) + row * 144 + seg * 16;
    }

    const int g  = tid >> 8;
    const int t2 = tid & 255;

    for (int t = 0; t < TT; t++) {
        const float* hcur = g_hbuf[t & 1];
        float* hnxt = g_hbuf[(t & 1) ^ 1];

        float cH[3][4] = {}, cS[3][4] = {};
        float4 aP;
        uint4 bP0, bP1, bP2;

        aP = *(const float4*)(hcur + (size_t)(a_b0 + l_arow) * HH + l_af4 * 4);
        bP0 = *(const uint4*)(b_basep[0] + b_off[0]);
        bP1 = *(const uint4*)(b_basep[1] + b_off[1]);
        bP2 = *(const uint4*)(b_basep[2] + b_off[2]);
        {
            uint32_t h01, l01, h23, l23;
            split2(aP.x, aP.y, h01, l01);
            split2(aP.z, aP.w, h23, l23);
            *(uint2*)(dsm + A_HI + a_dst) = make_uint2(h01, h23);
            *(uint2*)(dsm + A_LO + a_dst) = make_uint2(l01, l23);
            *(uint4*)(dsm + b_dst[0]) = bP0;
            *(uint4*)(dsm + b_dst[1]) = bP1;
            *(uint4*)(dsm + b_dst[2]) = bP2;
        }
        __syncthreads();

        for (int c = 0; c < NCH; c++) {
            const uint32_t bufs = sbase + (c & 1) * BUF_BYTES;
            if (c < NCH - 1) {
                int cn = c + 1;
                const float* asrc = (cn < 16)
                    ? (hcur + (size_t)(a_b0 + l_arow) * HH + cn * 64 + l_af4 * 4)
                    : (g_state + (size_t)(a_b0 + l_arow) * KK + l_af4 * 4);
                aP = *(const float4*)asrc;
                bP0 = *(const uint4*)(b_basep[0] + b_off[0] + cn * 64);
                bP1 = *(const uint4*)(b_basep[1] + b_off[1] + cn * 64);
                bP2 = *(const uint4*)(b_basep[2] + b_off[2] + cn * 64);
            }
            if (mmaw) {
                float (*cc)[4] = (c == 16) ? cS : cH;
#pragma unroll
                for (int ks = 0; ks < 4; ks++) {
                    uint32_t ah0, ah1, ah2, ah3, al0, al1, al2, al3;
                    ldm4(ah0, ah1, ah2, ah3, bufs + A_HI + aoff + ks * 32);
                    ldm4(al0, al1, al2, al3, bufs + A_LO + aoff + ks * 32);
                    uint32_t bh0, bh1, bh2, bh3, bh4, bh5;
                    ldm4(bh0, bh1, bh2, bh3, bufs + B_HI + boff4 + ks * 32);
                    ldm2(bh4, bh5,           bufs + B_HI + boff2 + ks * 32);
                    uint32_t bl0, bl1, bl2, bl3, bl4, bl5;
                    ldm4(bl0, bl1, bl2, bl3, bufs + B_LO + boff4 + ks * 32);
                    ldm2(bl4, bl5,           bufs + B_LO + boff2 + ks * 32);
                    mma_bf16(cc[0], ah0, ah1, ah2, ah3, bh0, bh1);
                    mma_bf16(cc[0], ah0, ah1, ah2, ah3, bl0, bl1);
                    mma_bf16(cc[0], al0, al1, al2, al3, bh0, bh1);
                    mma_bf16(cc[1], ah0, ah1, ah2, ah3, bh2, bh3);
                    mma_bf16(cc[1], ah0, ah1, ah2, ah3, bl2, bl3);
                    mma_bf16(cc[1], al0, al1, al2, al3, bh2, bh3);
                    mma_bf16(cc[2], ah0, ah1, ah2, ah3, bh4, bh5);
                    mma_bf16(cc[2], ah0, ah1, ah2, ah3, bl4, bl5);
                    mma_bf16(cc[2], al0, al1, al2, al3, bh4, bh5);
                }
            }
            if (c < NCH - 1) {
                char* nb = dsm + ((c + 1) & 1) * BUF_BYTES;
                uint32_t h01, l01, h23, l23;
                split2(aP.x, aP.y, h01, l01);
                split2(aP.z, aP.w, h23, l23);
                *(uint2*)(nb + A_HI + a_dst) = make_uint2(h01, h23);
                *(uint2*)(nb + A_LO + a_dst) = make_uint2(l01, l23);
                *(uint4*)(nb + b_dst[0]) = bP0;
                *(uint4*)(nb + b_dst[1]) = bP1;
                *(uint4*)(nb + b_dst[2]) = bP2;
            }
            __syncthreads();
        }

        {
            float* preH = shf;
            float* preS = shf + 96 * 33;
            if (mmaw) {
                const int rb = mt * 16 + (lane >> 2);
#pragma unroll
                for (int tau = 0; tau < 3; tau++) {
                    int jc = np * 24 + tau * 8 + (lane & 3) * 2;
                    preH[jc * 33 + rb]           = cH[tau][0];
                    preH[(jc + 1) * 33 + rb]     = cH[tau][1];
                    preH[jc * 33 + rb + 8]       = cH[tau][2];
                    preH[(jc + 1) * 33 + rb + 8] = cH[tau][3];
                    preS[jc * 33 + rb]           = cS[tau][0];
                    preS[(jc + 1) * 33 + rb]     = cS[tau][1];
                    preS[jc * 33 + rb + 8]       = cS[tau][2];
                    preS[(jc + 1) * 33 + rb + 8] = cS[tau][3];
                }
            }
            __syncthreads();

            const float* gx = g_Gx + ((size_t)t * BB + a_b0) * G3;
#pragma unroll
            for (int rep = 0; rep < 2; rep++) {
                int idx = tid + rep * 512;
                int b = idx >> 5, i = idx & 31;
                int ii = a_i0 + i;
                const float* gxb = gx + (size_t)b * G3;
                float Sr = preH[i * 33 + b] + preS[i * 33 + b] + gxb[ii] + bhh[ii];
                float Sz = preH[(32 + i) * 33 + b] + preS[(32 + i) * 33 + b] +
                           gxb[1024 + ii] + bhh[1024 + ii];
                float An = preS[(64 + i) * 33 + b] + gxb[2048 + ii];
                float Hn = preH[(64 + i) * 33 + b] + bhh[2048 + ii];
                float r = fsig(Sr);
                float z = fsig(Sz);
                float n = ftanh(An + r * Hn);
                hnxt[(size_t)(a_b0 + b) * HH + ii] =
                    (1.0f - z) * n + z * hcur[(size_t)(a_b0 + b) * HH + ii];
            }
        }
        gsync(bar++);

        {
            const int b_o0 = (blk & 31) * 16;
            const int bty = t2 >> 3;
            const int btx = t2 & 7;
            const int lr = t2 >> 2, lc = (t2 & 3) * 4;
            float c0 = 0.0f, c1 = 0.0f;
            for (int kt = 0; kt < 32; kt++) {
                int k0 = g * 512 + kt * 16;
                if (t2 < 128) {
                    float4 v = *(const float4*)&hnxt[(size_t)(a_b0 + lr) * HH + k0 + lc];
                    shf[g * 512 + (lc + 0) * 32 + lr] = v.x;
                    shf[g * 512 + (lc + 1) * 32 + lr] = v.y;
                    shf[g * 512 + (lc + 2) * 32 + lr] = v.z;
                    shf[g * 512 + (lc + 3) * 32 + lr] = v.w;
                }
                if (t2 < 64) {
                    int row = t2 >> 2, c = (t2 & 3) * 4;
                    float4 w = *(const float4*)&W1[(size_t)(b_o0 + row) * HH + k0 + c];
                    shf[1024 + g * 256 + (c + 0) * 16 + row] = w.x;
                    shf[1024 + g * 256 + (c + 1) * 16 + row] = w.y;
                    shf[1024 + g * 256 + (c + 2) * 16 + row] = w.z;
                    shf[1024 + g * 256 + (c + 3) * 16 + row] = w.w;
                }
                __syncthreads();
#pragma unroll
                for (int k = 0; k < 16; k++) {
                    float a = shf[g * 512 + k * 32 + bty];
                    float2 w = *(const float2*)&shf[1024 + g * 256 + k * 16 + btx * 2];
                    c0 += a * w.x; c1 += a * w.y;
                }
                __syncthreads();
            }
            if (g == 1) {
                shf[2048 + t2 * 2] = c0; shf[2048 + t2 * 2 + 1] = c1;
            }
            __syncthreads();
            if (g == 0) {
                c0 += shf[2048 + t2 * 2]; c1 += shf[2048 + t2 * 2 + 1];
                int b = a_b0 + bty, o = b_o0 + btx * 2;
                g_a1[b * HIDV + o]     = ftanh(c0 + b1[o]);
                g_a1[b * HIDV + o + 1] = ftanh(c1 + b1[o + 1]);
            }
        }
        gsync(bar++);

        {
            int b = blk;
            shf[tid] = g_a1[b * HIDV + tid];
            __syncthreads();
            int k = tid & 63, q = tid >> 6;
            const float* w = W2 + (size_t)k * HIDV + q * 64;
            const float* a = shf + q * 64;
            float p = 0.0f;
#pragma unroll 16
            for (int i = 0; i < 64; i++) p += a[i] * w[i];
            shf[512 + tid] = p;
            __syncthreads();
            if (tid < KK) {
                float lg = b2[tid];
#pragma unroll
                for (int q2 = 0; q2 < 8; q2++) lg += shf[512 + q2 * 64 + tid];
                out[((size_t)b * TT + t) * KK + tid] = lg;
                shf[1024 + tid] = fminf(fmaxf(lg, -10.0f), 10.0f);
            }
            __syncthreads();
            if (tid < 32) {
                float x0 = shf[1024 + tid], x1 = shf[1024 + tid + 32];
                float m = fmaxf(x0, x1);
#pragma unroll
                for (int o = 16; o; o >>= 1) m = fmaxf(m, __shfl_xor_sync(0xffffffffu, m, o));
                float e0 = expf(x0 - m), e1 = expf(x1 - m);
                float s = e0 + e1;
#pragma unroll
                for (int o = 16; o; o >>= 1) s += __shfl_xor_sync(0xffffffffu, s, o);
                float inv = 1.0f / s;
                g_state[b * KK + tid]      = e0 * inv;
                g_state[b * KK + tid + 32] = e1 * inv;
            }
        }
        gsync(bar++);
    }
}

// ---------------- host launch -----------------------------------------------
extern "C" void kernel_launch(void* const* d_in, const int* in_sizes, int n_in,
                              void* d_out, int out_size) {
    const float* ctx  = (const float*)d_in[0];   // [B,T,H]
    const float* init = (const float*)d_in[1];   // [B,K]
    const float* E    = (const float*)d_in[2];   // [K,S]
    const float* Wih  = (const float*)d_in[3];   // [3H,D]
    const float* Whh  = (const float*)d_in[4];   // [3H,H]
    const float* bih  = (const float*)d_in[5];   // [3H]
    const float* bhh  = (const float*)d_in[6];   // [3H]
    const float* W1   = (const float*)d_in[7];   // [HID,H]
    const float* b1   = (const float*)d_in[8];   // [HID]
    const float* W2   = (const float*)d_in[9];   // [K,HID]
    const float* b2   = (const float*)d_in[10];  // [K]
    float* out = (float*)d_out;                  // [B,T,K] fp32

    cudaFuncSetAttribute(k_seq, cudaFuncAttributeMaxDynamicSharedMemorySize, SMEM_DYN);

    k_init<<<512, 256>>>(init);
    k_prep<<<G3, 128>>>(Whh, E, Wih);
    k_prepw<<<G3, 256>>>(Wih);
    k_gx<<<dim3(G3 / 128, (BB * TT) / 128), 256>>>(ctx, bih);
    k_seq<<<GRID, NTHR, SMEM_DYN>>>(bhh, W1, b1, W2, b2, out);
}